// round 3
// baseline (speedup 1.0000x reference)
#include <cuda_runtime.h>
#include <cuda_fp16.h>

// RGBuvHistBlock: x [8,3,256,256] f32 in [0,1]; bin_vals [64] = linspace(-1,1).
// hist[nc][b] = sum_p exp(-((2x-1)-b)^2/(2*0.02^2)), normalized per nc.
//
// R3: f16x2 MUFU. Per 2 pixels x 1 bin:
//   arg_pair = 2s*t - t^2 - s^2   (packed f32x2 fma + add, cancellation-safe)
//   h = cvt.rn.f16x2.f32(arg)     (1 op)
//   w = ex2.approx.f16x2(h)       (1 MUFU op = 2 exps)
//   acc = hadd2(acc, w), flushed to f32 every 32 pairs.
// MUFU-bound at 4 cyc/pixel-bin (was 8).

#define NC_TOTAL   24
#define PIX_PER_NC 65536
#define HB         64
#define SPLITS     64
#define CHUNK      1024
#define PAIRS_PG   256           // pairs per group (512 pixels / group, 2 groups)

// s = SA*(2x-1);  weight = 2^{-(s-t)^2};  SA = sqrt(1250*log2(e))
#define SA   42.46608994f
#define SA2  84.93217988f

__device__ float    g_part[NC_TOTAL * SPLITS * HB];
__device__ unsigned g_cnt[NC_TOTAL];

__device__ __forceinline__ unsigned long long packf2(float lo, float hi) {
    unsigned long long r;
    asm("mov.b64 %0, {%1,%2};" : "=l"(r) : "f"(lo), "f"(hi));
    return r;
}

__global__ __launch_bounds__(128) void hist_fused_kernel(
    const float* __restrict__ x, const float* __restrict__ bin_vals,
    float* __restrict__ out)
{
    const int nc    = blockIdx.y;
    const int split = blockIdx.x;
    const int tid   = threadIdx.x;
    const int bin   = tid & (HB - 1);
    const int grp   = tid >> 6;                 // 0..1

    __shared__ ulonglong2 sx[2 * PAIRS_PG];     // 512 pairs * 16B = 8KB: (2s pair, -s^2 pair)
    __shared__ float      racc[128];
    __shared__ float      ws[2];
    __shared__ int        slast;

    // Stage: per pixel compute s, store packed (2s0,2s1 | -sq0,-sq1) per pair.
    {
        const float4* xp = reinterpret_cast<const float4*>(
            x + (size_t)nc * PIX_PER_NC + (size_t)split * CHUNK);
#pragma unroll
        for (int h = 0; h < 2; ++h) {
            float4 v = xp[tid + h * 128];
            float s0 = fmaf(v.x, SA2, -SA);
            float s1 = fmaf(v.y, SA2, -SA);
            float s2 = fmaf(v.z, SA2, -SA);
            float s3 = fmaf(v.w, SA2, -SA);
            ulonglong2 p0, p1;
            p0.x = packf2(s0 + s0, s1 + s1);
            p0.y = packf2(-s0 * s0, -s1 * s1);
            p1.x = packf2(s2 + s2, s3 + s3);
            p1.y = packf2(-s2 * s2, -s3 * s3);
            sx[2 * tid + h * 256]     = p0;
            sx[2 * tid + h * 256 + 1] = p1;
        }
    }

    const float t  = SA * bin_vals[bin];
    const unsigned long long tt  = packf2(t, t);
    const unsigned long long ntt = packf2(-t * t, -t * t);

    __syncthreads();

    const ulonglong2* base = sx + grp * PAIRS_PG;
    float fa0 = 0.0f, fa1 = 0.0f;

    for (int o = 0; o < PAIRS_PG; o += 32) {
        __half2 acch = __float2half2_rn(0.0f);
#pragma unroll
        for (int i = 0; i < 32; ++i) {
            ulonglong2 v = base[o + i];          // broadcast LDS.128
            unsigned long long a1, arg;
            asm("fma.rn.f32x2 %0, %1, %2, %3;" : "=l"(a1)  : "l"(v.x), "l"(tt), "l"(ntt));
            asm("add.rn.f32x2 %0, %1, %2;"     : "=l"(arg) : "l"(a1), "l"(v.y));
            float lo, hi;
            asm("mov.b64 {%0,%1}, %2;" : "=f"(lo), "=f"(hi) : "l"(arg));
            unsigned h, w;
            asm("cvt.rn.f16x2.f32 %0, %1, %2;" : "=r"(h) : "f"(hi), "f"(lo));
            asm("ex2.approx.f16x2 %0, %1;"     : "=r"(w) : "r"(h));
            __half2 wh = *reinterpret_cast<__half2*>(&w);
            acch = __hadd2(acch, wh);
        }
        float2 f = __half22float2(acch);
        fa0 += f.x;
        fa1 += f.y;
    }

    racc[tid] = fa0 + fa1;
    __syncthreads();

    if (tid < HB)
        g_part[((size_t)nc * SPLITS + split) * HB + tid] = racc[tid] + racc[tid + 64];
    __syncthreads();

    // Last block per nc reduces + normalizes.
    if (tid == 0) {
        __threadfence();
        unsigned old = atomicAdd(&g_cnt[nc], 1u);
        slast = (old == SPLITS - 1);
    }
    __syncthreads();
    if (!slast) return;
    __threadfence();

    float bsum = 0.0f;
    if (tid < HB) {
        const float* p = g_part + (size_t)nc * SPLITS * HB + bin;
#pragma unroll 8
        for (int sp = 0; sp < SPLITS; ++sp)
            bsum += p[(size_t)sp * HB];
    }
    float v = (tid < HB) ? bsum : 0.0f;
    float r = v;
#pragma unroll
    for (int o = 16; o; o >>= 1) r += __shfl_xor_sync(0xffffffffu, r, o);
    if (tid == 0)  ws[0] = r;
    if (tid == 32) ws[1] = r;
    __syncthreads();
    float tot = ws[0] + ws[1];

    if (tid < HB)
        out[nc * HB + tid] = v / (tot + 1e-8f);

    if (tid == 0) g_cnt[nc] = 0;
}

extern "C" void kernel_launch(void* const* d_in, const int* in_sizes, int n_in,
                              void* d_out, int out_size) {
    const float* x        = (const float*)d_in[0];
    const float* bin_vals = (const float*)d_in[1];
    float* out            = (float*)d_out;

    dim3 grid(SPLITS, NC_TOTAL);
    hist_fused_kernel<<<grid, 128>>>(x, bin_vals, out);
}

// round 5
// speedup vs baseline: 2.3027x; 2.3027x over previous
#include <cuda_runtime.h>

// RGBuvHistBlock: x [8,3,256,256] f32 in [0,1]; bin_vals [64] = linspace(-1,1).
// hist[nc][b] = sum_p exp(-((2x-1)-b)^2/(2*0.02^2)), normalized per nc.
//
// R5: windowed scatter (R4) with the block-reduce rotation bug fixed
// (rotate by bin index b, not tid; the tid rotation made the two halves
// sum the SAME 64 cells -> 2.1e-2 rel_err).
// Weight at k bins away = exp(-1.26 k^2): k=3 -> 1.2e-5, k>=4 -> <2e-9,
// so each pixel touches 7 bins. Per-thread private SMEM histograms
// (hist[bin*128+tid]) -> no atomics, conflict-free by layout.

#define NC_TOTAL   24
#define PIX_PER_NC 65536
#define HB         64
#define SPLITS     16
#define CHUNK      4096          // pixels per block
#define NT         128           // threads per block
#define WIN        7             // window bins (+-3)

// s = SA*(2x-1); weight = 2^{-(s-t)^2}; SA = sqrt(1250*log2(e))
#define SA   42.46608994f
#define SA2  84.93217988f
#define DS   1.34812984f         // SA * 2/63 (scaled bin spacing)

__device__ float    g_part[NC_TOTAL * SPLITS * HB];
__device__ unsigned g_cnt[NC_TOTAL];

__device__ __forceinline__ float ex2f(float a) {
    float r;
    asm("ex2.approx.ftz.f32 %0, %1;" : "=f"(r) : "f"(a));
    return r;
}

__global__ __launch_bounds__(NT) void hist_fused_kernel(
    const float* __restrict__ x, const float* __restrict__ bin_vals,
    float* __restrict__ out)
{
    const int nc    = blockIdx.y;
    const int split = blockIdx.x;
    const int tid   = threadIdx.x;

    __shared__ float hist[HB * NT];     // 32KB per-thread private hists
    __shared__ float racc[NT];
    __shared__ float ws[2];
    __shared__ int   slast;

    // Zero private hists (16 STS.128 per thread).
    {
        float4* hz = reinterpret_cast<float4*>(hist);
#pragma unroll
        for (int i = 0; i < (HB * NT / 4) / NT; ++i)
            hz[tid + i * NT] = make_float4(0.f, 0.f, 0.f, 0.f);
    }
    __syncthreads();

    const float4* xp = reinterpret_cast<const float4*>(
        x + (size_t)nc * PIX_PER_NC + (size_t)split * CHUNK);

#pragma unroll 2
    for (int it = 0; it < CHUNK / (4 * NT); ++it) {
        float4 v = xp[tid + it * NT];
        float pv[4] = {v.x, v.y, v.z, v.w};
#pragma unroll
        for (int p = 0; p < 4; ++p) {
            float vf = pv[p];
            float s  = fmaf(vf, SA2, -SA);          // scaled coordinate
            int j0   = __float2int_rn(vf * 63.0f);
            int jc   = min(max(j0, 3), 60);         // window center, fully in-range
            float a  = fmaf((float)(jc - 3), -DS, s + SA);  // d at k=0

            float h[WIN], w[WIN];
            const int base = (jc - 3) * NT + tid;
#pragma unroll
            for (int k = 0; k < WIN; ++k)           // 7 loads first (distinct cells)
                h[k] = hist[base + k * NT];
#pragma unroll
            for (int k = 0; k < WIN; ++k) {
                float d = fmaf((float)k, -DS, a);
                w[k] = ex2f(-d * d);
            }
#pragma unroll
            for (int k = 0; k < WIN; ++k)           // then 7 stores
                hist[base + k * NT] = h[k] + w[k];
        }
    }
    __syncthreads();

    // Block reduce: bin b = tid&63, half = tid>>6. Thread (b,0) sums cells
    // {b..b+63}, thread (b,1) sums {b+64..b+127} (mod 128): disjoint, complete,
    // conflict-free (cell mod 32 distinct within each warp).
    {
        const int b    = tid & (HB - 1);
        const int half = tid >> 6;
        float acc = 0.0f;
        const float* hb = hist + b * NT;
#pragma unroll 8
        for (int i = 0; i < 64; ++i)
            acc += hb[(half * 64 + i + b) & (NT - 1)];
        racc[tid] = acc;
    }
    __syncthreads();

    if (tid < HB)
        g_part[((size_t)nc * SPLITS + split) * HB + tid] = racc[tid] + racc[tid + 64];
    __syncthreads();

    // Last block per nc reduces + normalizes.
    if (tid == 0) {
        __threadfence();
        unsigned old = atomicAdd(&g_cnt[nc], 1u);
        slast = (old == SPLITS - 1);
    }
    __syncthreads();
    if (!slast) return;
    __threadfence();

    float bsum = 0.0f;
    if (tid < HB) {
        const float* p = g_part + (size_t)nc * SPLITS * HB + tid;
#pragma unroll
        for (int sp = 0; sp < SPLITS; ++sp)
            bsum += p[(size_t)sp * HB];
    }
    float v = (tid < HB) ? bsum : 0.0f;
    float r = v;
#pragma unroll
    for (int o = 16; o; o >>= 1) r += __shfl_xor_sync(0xffffffffu, r, o);
    if (tid == 0)  ws[0] = r;
    if (tid == 32) ws[1] = r;
    __syncthreads();
    float tot = ws[0] + ws[1];

    if (tid < HB)
        out[nc * HB + tid] = v / (tot + 1e-8f);

    if (tid == 0) g_cnt[nc] = 0;   // reset for next graph replay
}

extern "C" void kernel_launch(void* const* d_in, const int* in_sizes, int n_in,
                              void* d_out, int out_size) {
    const float* x        = (const float*)d_in[0];
    const float* bin_vals = (const float*)d_in[1];
    float* out            = (float*)d_out;

    dim3 grid(SPLITS, NC_TOTAL);
    hist_fused_kernel<<<grid, NT>>>(x, bin_vals, out);
}